// round 5
// baseline (speedup 1.0000x reference)
#include <cuda_runtime.h>
#include <math.h>

#define D 64
#define C 128
#define H 512
#define BATCH 4096
#define TM 16
#define NTHREADS 256

typedef unsigned long long u64;

__device__ __forceinline__ u64 pack2(float lo, float hi) {
    u64 r; asm("mov.b64 %0, {%1, %2};" : "=l"(r) : "f"(lo), "f"(hi)); return r;
}
__device__ __forceinline__ u64 dup2(float x) {
    u64 r; asm("mov.b64 %0, {%1, %1};" : "=l"(r) : "f"(x)); return r;
}
__device__ __forceinline__ void fma2(u64& acc, u64 a, u64 b) {
    asm("fma.rn.f32x2 %0, %1, %2, %0;" : "+l"(acc) : "l"(a), "l"(b));
}
__device__ __forceinline__ void unpack2(float& lo, float& hi, u64 v) {
    asm("mov.b64 {%0, %1}, %2;" : "=f"(lo), "=f"(hi) : "l"(v));
}
__device__ __forceinline__ void ldg_v2b64(u64& a, u64& b, const float* p) {
    asm("ld.global.nc.v2.b64 {%0, %1}, [%2];" : "=l"(a), "=l"(b) : "l"(p));
}

// Permuted + masked weights (built by prep kernel each launch; idempotent).
__device__ float g_W1p[(D + C) * H];   // [in][p]  in-major, masked, hidden perm
__device__ float g_W2p[H * H];         // [j][p]   j = reduction dim (sorted), p sorted
__device__ float g_W3pp[D * H * 2];    // [i][p][2] (mean col i, prescale col D+i), masked
__device__ float g_b1p[H];
__device__ float g_b2p[H];

// Hidden degrees: m_h[k] = (k % 63) + 1. Sorted by degree ascending (ties by k).
__device__ __forceinline__ int permk(int p) {
    if (p < 72) { int d = p / 9; int t = p - 9 * d; return d + 63 * t; }
    int q = p - 72; int d8 = q >> 3; int t = q & 7; return 8 + d8 + 63 * t;
}
__device__ __forceinline__ int degp(int p) {
    return (p < 72) ? (p / 9 + 1) : ((p - 72) / 8 + 9);
}
__device__ __forceinline__ int cntd(int d) {
    return (d <= 0) ? 0 : (d <= 8 ? 9 * d : 8 * d + 8);
}

__global__ void prep_kernel(const float* __restrict__ W1, const float* __restrict__ b1,
                            const float* __restrict__ W2, const float* __restrict__ b2,
                            const float* __restrict__ W3) {
    const int NA = (D + C) * H;
    const int NB = H * H;
    const int NC = D * H;
    const int total = NA + NB + NC + 2 * H;
    for (int idx = blockIdx.x * blockDim.x + threadIdx.x; idx < total;
         idx += gridDim.x * blockDim.x) {
        if (idx < NA) {
            int in = idx >> 9, p = idx & 511;
            float m = (in < D) ? ((degp(p) >= in + 1) ? 1.f : 0.f) : 1.f;
            g_W1p[idx] = W1[in * H + permk(p)] * m;
        } else if (idx < NA + NB) {
            int t = idx - NA;
            int j = t >> 9, p = t & 511;
            g_W2p[t] = (degp(p) >= degp(j)) ? W2[permk(j) * H + permk(p)] : 0.f;
        } else if (idx < NA + NB + NC) {
            int t = idx - NA - NB;
            int i = t >> 9, p = t & 511;
            int k = permk(p);
            bool m = (degp(p) <= i);   // m_out = i+1 > deg  <=>  deg <= i
            g_W3pp[t * 2 + 0] = m ? W3[k * (2 * D) + i] : 0.f;
            g_W3pp[t * 2 + 1] = m ? W3[k * (2 * D) + D + i] : 0.f;
        } else {
            int t = idx - NA - NB - NC;
            if (t < H) g_b1p[t] = b1[permk(t)];
            else       g_b2p[t - H] = b2[permk(t - H)];
        }
    }
}

// Dynamic smem layout (floats):
//   h1s[H*TM]  : h1 (pre-act until finalized, then relu'd in place) [p][r]  32KB
//   ctx[C*TM]  : context, TRANSPOSED [c][r]                                  8KB
//   zsh[TM]    : z values of current step
//   red[2*TM]  : per-row mean (0..15) / prescale (16..31) partials
#define SMEM_FLOATS (H * TM + C * TM + TM + 2 * TM)
#define SMEM_BYTES (SMEM_FLOATS * 4)

__global__ __launch_bounds__(NTHREADS, 2)
void made_main(const float* __restrict__ qc, const float* __restrict__ eps,
               const float* __restrict__ b3, float* __restrict__ out) {
    extern __shared__ float sm[];
    float* h1s = sm;                 // [512][16]
    float* ctx = sm + H * TM;        // [128][16]
    float* zsh = ctx + C * TM;       // [16]
    float* red = zsh + TM;           // [32]

    const int tid  = threadIdx.x;
    const int r0   = blockIdx.x * TM;
    const int warp = tid >> 5, lane = tid & 31;
    const int rg    = lane & 3;               // row group: rows rg*4..rg*4+3
    const int cg    = lane >> 2;              // 0..7: col sub-offset cg*4
    const int rbase = rg << 2;

    // ---- stage context transposed: ctx[c][r] ----
    for (int idx = tid; idx < TM * C; idx += NTHREADS) {
        int r = idx >> 7, c = idx & 127;
        ctx[c * TM + r] = qc[(r0 + r) * C + c];
    }
    if (tid < 2 * TM) red[tid] = 0.f;
    __syncthreads();

    // ---- h1_pre init: each thread owns 2 hidden units p, all 16 rows ----
    for (int p = tid; p < H; p += NTHREADS) {
        float acc[TM];
        float b = __ldg(&g_b1p[p]);
#pragma unroll
        for (int r = 0; r < TM; ++r) acc[r] = b;
        for (int c = 0; c < C; ++c) {
            float w = __ldg(&g_W1p[(D + c) * H + p]);
            float4 x0 = *(const float4*)&ctx[c * TM + 0];
            float4 x1 = *(const float4*)&ctx[c * TM + 4];
            float4 x2 = *(const float4*)&ctx[c * TM + 8];
            float4 x3 = *(const float4*)&ctx[c * TM + 12];
            acc[0]  += x0.x * w; acc[1]  += x0.y * w; acc[2]  += x0.z * w; acc[3]  += x0.w * w;
            acc[4]  += x1.x * w; acc[5]  += x1.y * w; acc[6]  += x1.z * w; acc[7]  += x1.w * w;
            acc[8]  += x2.x * w; acc[9]  += x2.y * w; acc[10] += x2.z * w; acc[11] += x2.w * w;
            acc[12] += x3.x * w; acc[13] += x3.y * w; acc[14] += x3.z * w; acc[15] += x3.w * w;
        }
#pragma unroll
        for (int r = 0; r < TM; ++r) h1s[p * TM + r] = acc[r];
    }

    // ---- 64 autoregressive steps ----
    for (int i = 0; i < D; ++i) {
        __syncthreads();   // prev h1 update + red reset visible
        const int n2   = cntd(i);             // needed h2 cols = sorted prefix
        const int nwin = (n2 + 31) >> 5;      // 32-col windows in use (<=16)
        float mm[4] = {0.f, 0.f, 0.f, 0.f};
        float pp[4] = {0.f, 0.f, 0.f, 0.f};
        bool any = false;

        // Serpentine load-balanced window assignment: warp w handles windows
        // {nwin-1-w, nwin-16+w} (those >= 0).
#pragma unroll
        for (int s = 0; s < 2; ++s) {
            const int w = (s == 0) ? (nwin - 1 - warp) : (nwin - 16 + warp);
            if (w < 0) continue;               // warp-uniform predicate
            any = true;
            const int wb = w << 5;
            const int lastneed = min(wb + 31, n2 - 1);
            const int jlimW = min(H, (cntd(degp(lastneed)) + 7) & ~7);
            const int mycol = wb + (cg << 2);

            // acc[r][cp]: 4 rows x 2 col-pairs, packed f32x2
            float4 b2v = __ldg((const float4*)&g_b2p[mycol]);
            u64 bp0 = pack2(b2v.x, b2v.y), bp1 = pack2(b2v.z, b2v.w);
            u64 acc[4][2];
#pragma unroll
            for (int rr = 0; rr < 4; ++rr) { acc[rr][0] = bp0; acc[rr][1] = bp1; }

            const float* w2base = g_W2p + mycol;
            const float* hbase  = h1s + rbase;

            for (int jc = 0; jc < jlimW; jc += 8) {
                u64 wv[8][2]; float4 h[8];
#pragma unroll
                for (int u = 0; u < 8; ++u)
                    ldg_v2b64(wv[u][0], wv[u][1], w2base + (jc + u) * H);
#pragma unroll
                for (int u = 0; u < 8; ++u)
                    h[u] = *(const float4*)&hbase[(jc + u) * TM];
#pragma unroll
                for (int u = 0; u < 8; ++u) {
                    u64 h0 = dup2(h[u].x), h1 = dup2(h[u].y);
                    u64 h2 = dup2(h[u].z), h3 = dup2(h[u].w);
                    fma2(acc[0][0], h0, wv[u][0]); fma2(acc[0][1], h0, wv[u][1]);
                    fma2(acc[1][0], h1, wv[u][0]); fma2(acc[1][1], h1, wv[u][1]);
                    fma2(acc[2][0], h2, wv[u][0]); fma2(acc[2][1], h2, wv[u][1]);
                    fma2(acc[3][0], h3, wv[u][0]); fma2(acc[3][1], h3, wv[u][1]);
                }
            }

            // relu + project onto W3 cols (i, D+i); masked W3 zeroes out
            // cols with deg > i (their garbage h2 is harmless & finite).
            const float* w3 = g_W3pp + (((i << 9) + mycol) << 1);
            float4 wA = __ldg((const float4*)w3);        // (m0,p0,m1,p1)
            float4 wB = __ldg((const float4*)(w3 + 4));  // (m2,p2,m3,p3)
#pragma unroll
            for (int rr = 0; rr < 4; ++rr) {
                float a0, a1, a2, a3;
                unpack2(a0, a1, acc[rr][0]);
                unpack2(a2, a3, acc[rr][1]);
                float h2v;
                h2v = fmaxf(a0, 0.f); mm[rr] += h2v * wA.x; pp[rr] += h2v * wA.y;
                h2v = fmaxf(a1, 0.f); mm[rr] += h2v * wA.z; pp[rr] += h2v * wA.w;
                h2v = fmaxf(a2, 0.f); mm[rr] += h2v * wB.x; pp[rr] += h2v * wB.y;
                h2v = fmaxf(a3, 0.f); mm[rr] += h2v * wB.z; pp[rr] += h2v * wB.w;
            }
        }

        if (any) {
            // reduce over 8 col-groups within the warp (lane bits 2,3,4)
#pragma unroll
            for (int rr = 0; rr < 4; ++rr) {
                mm[rr] += __shfl_xor_sync(0xffffffffu, mm[rr], 4);
                mm[rr] += __shfl_xor_sync(0xffffffffu, mm[rr], 8);
                mm[rr] += __shfl_xor_sync(0xffffffffu, mm[rr], 16);
                pp[rr] += __shfl_xor_sync(0xffffffffu, pp[rr], 4);
                pp[rr] += __shfl_xor_sync(0xffffffffu, pp[rr], 8);
                pp[rr] += __shfl_xor_sync(0xffffffffu, pp[rr], 16);
            }
            if (lane < 4) {
#pragma unroll
                for (int rr = 0; rr < 4; ++rr) {
                    atomicAdd(&red[rbase + rr], mm[rr]);
                    atomicAdd(&red[TM + rbase + rr], pp[rr]);
                }
            }
        }
        __syncthreads();

        if (tid < TM) {
            float mean = red[tid] + b3[i];
            float pres = red[TM + tid] + b3[D + i];
            // stable softplus = max(x,0) + log1p(exp(-|x|))
            float sp = fmaxf(pres, 0.f) + log1pf(expf(-fabsf(pres)));
            float z = mean + sp * eps[(r0 + tid) * D + i];
            out[(r0 + tid) * D + i] = z;
            zsh[tid] = z;
            red[tid] = 0.f;                 // reset for next step
            red[TM + tid] = 0.f;
        }
        __syncthreads();

        // rank-1 h1 update: hidden units with deg >= i+1 (sorted suffix).
        // Rows with deg == i+1 are now finalized -> apply relu in place.
        const int s0  = n2;
        const int fin = cntd(i + 1);
        const int nupd = (H - s0) * TM;
        for (int u = tid; u < nupd; u += NTHREADS) {
            int p = s0 + (u >> 4), r = u & 15;
            float v = h1s[p * TM + r] + zsh[r] * __ldg(&g_W1p[i * H + p]);
            if (p < fin) v = fmaxf(v, 0.f);
            h1s[p * TM + r] = v;
        }
        // top-of-loop __syncthreads orders update before next step's reads
    }
}

extern "C" void kernel_launch(void* const* d_in, const int* in_sizes, int n_in,
                              void* d_out, int out_size) {
    const float* q   = (const float*)d_in[0];  // (4096, 128)
    const float* eps = (const float*)d_in[1];  // (4096, 64)
    const float* W1  = (const float*)d_in[2];  // (192, 512)
    const float* b1  = (const float*)d_in[3];  // (512,)
    const float* W2  = (const float*)d_in[4];  // (512, 512)
    const float* b2  = (const float*)d_in[5];  // (512,)
    const float* W3  = (const float*)d_in[6];  // (512, 128)
    const float* b3  = (const float*)d_in[7];  // (128,)
    float* out = (float*)d_out;                // (4096, 64)

    cudaFuncSetAttribute(made_main, cudaFuncAttributeMaxDynamicSharedMemorySize,
                         SMEM_BYTES);

    prep_kernel<<<408, 256>>>(W1, b1, W2, b2, W3);
    made_main<<<BATCH / TM, NTHREADS, SMEM_BYTES>>>(q, eps, b3, out);
}

// round 6
// speedup vs baseline: 1.0693x; 1.0693x over previous
#include <cuda_runtime.h>
#include <math.h>

#define D 64
#define C 128
#define H 512
#define BATCH 4096
#define TM 16
#define NTHREADS 256

typedef unsigned long long u64;

__device__ __forceinline__ u64 pack2(float lo, float hi) {
    u64 r; asm("mov.b64 %0, {%1, %2};" : "=l"(r) : "f"(lo), "f"(hi)); return r;
}
__device__ __forceinline__ u64 dup2(float x) {
    u64 r; asm("mov.b64 %0, {%1, %1};" : "=l"(r) : "f"(x)); return r;
}
__device__ __forceinline__ void fma2(u64& acc, u64 a, u64 b) {
    asm("fma.rn.f32x2 %0, %1, %2, %0;" : "+l"(acc) : "l"(a), "l"(b));
}
__device__ __forceinline__ void unpack2(float& lo, float& hi, u64 v) {
    asm("mov.b64 {%0, %1}, %2;" : "=f"(lo), "=f"(hi) : "l"(v));
}
__device__ __forceinline__ void ldg_v2b64(u64& a, u64& b, const float* p) {
    asm("ld.global.nc.v2.b64 {%0, %1}, [%2];" : "=l"(a), "=l"(b) : "l"(p));
}

// Permuted + masked weights (built by prep kernel each launch; idempotent).
__device__ float g_W1p[(D + C) * H];   // [in][p]  in-major, masked, hidden perm
__device__ float g_W2p[H * H];         // [j][p]   j = reduction dim (sorted), p sorted
__device__ float g_W3pp[D * H * 2];    // [i][p][2] (mean col i, prescale col D+i), masked
__device__ float g_b1p[H];
__device__ float g_b2p[H];

// Hidden degrees: m_h[k] = (k % 63) + 1. Sorted by degree ascending (ties by k).
__device__ __forceinline__ int permk(int p) {
    if (p < 72) { int d = p / 9; int t = p - 9 * d; return d + 63 * t; }
    int q = p - 72; int d8 = q >> 3; int t = q & 7; return 8 + d8 + 63 * t;
}
__device__ __forceinline__ int degp(int p) {
    return (p < 72) ? (p / 9 + 1) : ((p - 72) / 8 + 9);
}
__device__ __forceinline__ int cntd(int d) {
    return (d <= 0) ? 0 : (d <= 8 ? 9 * d : 8 * d + 8);
}

__global__ void prep_kernel(const float* __restrict__ W1, const float* __restrict__ b1,
                            const float* __restrict__ W2, const float* __restrict__ b2,
                            const float* __restrict__ W3) {
    const int NA = (D + C) * H;
    const int NB = H * H;
    const int NC = D * H;
    const int total = NA + NB + NC + 2 * H;
    for (int idx = blockIdx.x * blockDim.x + threadIdx.x; idx < total;
         idx += gridDim.x * blockDim.x) {
        if (idx < NA) {
            int in = idx >> 9, p = idx & 511;
            float m = (in < D) ? ((degp(p) >= in + 1) ? 1.f : 0.f) : 1.f;
            g_W1p[idx] = W1[in * H + permk(p)] * m;
        } else if (idx < NA + NB) {
            int t = idx - NA;
            int j = t >> 9, p = t & 511;
            g_W2p[t] = (degp(p) >= degp(j)) ? W2[permk(j) * H + permk(p)] : 0.f;
        } else if (idx < NA + NB + NC) {
            int t = idx - NA - NB;
            int i = t >> 9, p = t & 511;
            int k = permk(p);
            bool m = (degp(p) <= i);   // m_out = i+1 > deg  <=>  deg <= i
            g_W3pp[t * 2 + 0] = m ? W3[k * (2 * D) + i] : 0.f;
            g_W3pp[t * 2 + 1] = m ? W3[k * (2 * D) + D + i] : 0.f;
        } else {
            int t = idx - NA - NB - NC;
            if (t < H) g_b1p[t] = b1[permk(t)];
            else       g_b2p[t - H] = b2[permk(t - H)];
        }
    }
}

// Dynamic smem layout (floats):
//   h1s[H*TM]  : h1 (pre-act until finalized, then relu'd in place) [p][r]  32KB
//   ctx[C*TM]  : context, TRANSPOSED [c][r]                                  8KB
//   zsh[TM]    : z values of current step
//   red[2*TM]  : per-row mean (0..15) / prescale (16..31) partials
#define SMEM_FLOATS (H * TM + C * TM + TM + 2 * TM)
#define SMEM_BYTES (SMEM_FLOATS * 4)

// Depth-4 load/compute macros for the software pipeline.
#define LOADW(buf, jrow) do {                                               \
    _Pragma("unroll")                                                       \
    for (int u = 0; u < 4; ++u)                                             \
        ldg_v2b64(buf[u][0], buf[u][1], w2base + ((jrow) + u) * H);         \
} while (0)
#define LOADH(hbuf, jrow) do {                                              \
    _Pragma("unroll")                                                       \
    for (int u = 0; u < 4; ++u)                                             \
        hbuf[u] = *(const float4*)&hbase[((jrow) + u) * TM];                \
} while (0)
#define COMPUTE(buf, hbuf) do {                                             \
    _Pragma("unroll")                                                       \
    for (int u = 0; u < 4; ++u) {                                           \
        u64 d0 = dup2(hbuf[u].x), d1 = dup2(hbuf[u].y);                     \
        u64 d2 = dup2(hbuf[u].z), d3 = dup2(hbuf[u].w);                     \
        fma2(acc[0][0], d0, buf[u][0]); fma2(acc[0][1], d0, buf[u][1]);     \
        fma2(acc[1][0], d1, buf[u][0]); fma2(acc[1][1], d1, buf[u][1]);     \
        fma2(acc[2][0], d2, buf[u][0]); fma2(acc[2][1], d2, buf[u][1]);     \
        fma2(acc[3][0], d3, buf[u][0]); fma2(acc[3][1], d3, buf[u][1]);     \
    }                                                                       \
} while (0)

__global__ __launch_bounds__(NTHREADS, 2)
void made_main(const float* __restrict__ qc, const float* __restrict__ eps,
               const float* __restrict__ b3, float* __restrict__ out) {
    extern __shared__ float sm[];
    float* h1s = sm;                 // [512][16]
    float* ctx = sm + H * TM;        // [128][16]
    float* zsh = ctx + C * TM;       // [16]
    float* red = zsh + TM;           // [32]

    const int tid  = threadIdx.x;
    const int r0   = blockIdx.x * TM;
    const int warp = tid >> 5, lane = tid & 31;
    const int rg    = lane & 3;               // row group: rows rg*4..rg*4+3
    const int cg    = lane >> 2;              // 0..7: col sub-offset cg*4
    const int rbase = rg << 2;

    // ---- stage context transposed: ctx[c][r] ----
    for (int idx = tid; idx < TM * C; idx += NTHREADS) {
        int r = idx >> 7, c = idx & 127;
        ctx[c * TM + r] = qc[(r0 + r) * C + c];
    }
    if (tid < 2 * TM) red[tid] = 0.f;
    __syncthreads();

    // ---- h1_pre init: each thread owns 2 hidden units p, all 16 rows ----
    for (int p = tid; p < H; p += NTHREADS) {
        float acc[TM];
        float b = __ldg(&g_b1p[p]);
#pragma unroll
        for (int r = 0; r < TM; ++r) acc[r] = b;
        for (int c = 0; c < C; ++c) {
            float w = __ldg(&g_W1p[(D + c) * H + p]);
            float4 x0 = *(const float4*)&ctx[c * TM + 0];
            float4 x1 = *(const float4*)&ctx[c * TM + 4];
            float4 x2 = *(const float4*)&ctx[c * TM + 8];
            float4 x3 = *(const float4*)&ctx[c * TM + 12];
            acc[0]  += x0.x * w; acc[1]  += x0.y * w; acc[2]  += x0.z * w; acc[3]  += x0.w * w;
            acc[4]  += x1.x * w; acc[5]  += x1.y * w; acc[6]  += x1.z * w; acc[7]  += x1.w * w;
            acc[8]  += x2.x * w; acc[9]  += x2.y * w; acc[10] += x2.z * w; acc[11] += x2.w * w;
            acc[12] += x3.x * w; acc[13] += x3.y * w; acc[14] += x3.z * w; acc[15] += x3.w * w;
        }
#pragma unroll
        for (int r = 0; r < TM; ++r) h1s[p * TM + r] = acc[r];
    }

    // ---- 64 autoregressive steps ----
    for (int i = 0; i < D; ++i) {
        __syncthreads();   // prev h1 update + red reset visible
        const int n2   = cntd(i);             // needed h2 cols = sorted prefix
        const int nwin = (n2 + 31) >> 5;      // 32-col windows in use (<=16)
        float mm[4] = {0.f, 0.f, 0.f, 0.f};
        float pp[4] = {0.f, 0.f, 0.f, 0.f};
        bool any = false;

        // Serpentine load-balanced window assignment: warp w handles windows
        // {nwin-1-w, nwin-16+w} (those >= 0).
#pragma unroll
        for (int s = 0; s < 2; ++s) {
            const int w = (s == 0) ? (nwin - 1 - warp) : (nwin - 16 + warp);
            if (w < 0) continue;               // warp-uniform predicate
            any = true;
            const int wb = w << 5;
            const int lastneed = min(wb + 31, n2 - 1);
            // multiple of 16, >= 16 (min unrounded jlim is 9); rounded rows are
            // exactly zero in needed cols via the masked W2p.
            const int jlimW = min(H, (cntd(degp(lastneed)) + 15) & ~15);
            const int mycol = wb + (cg << 2);

            // acc[r][cp]: 4 rows x 2 col-pairs, packed f32x2
            float4 b2v = __ldg((const float4*)&g_b2p[mycol]);
            u64 bp0 = pack2(b2v.x, b2v.y), bp1 = pack2(b2v.z, b2v.w);
            u64 acc[4][2];
#pragma unroll
            for (int rr = 0; rr < 4; ++rr) { acc[rr][0] = bp0; acc[rr][1] = bp1; }

            const float* w2base = g_W2p + mycol;
            const float* hbase  = h1s + rbase;

            // Software-pipelined GEMM: depth-4 batches, double-buffered so
            // batch k+1's loads issue before batch k's compute.
            u64 wvA[4][2], wvB[4][2];
            float4 hA[4], hB[4];
            LOADW(wvA, 0); LOADH(hA, 0);
            int jc = 0;
            for (; jc + 8 < jlimW; jc += 8) {
                LOADW(wvB, jc + 4); LOADH(hB, jc + 4);
                COMPUTE(wvA, hA);
                LOADW(wvA, jc + 8); LOADH(hA, jc + 8);
                COMPUTE(wvB, hB);
            }
            LOADW(wvB, jc + 4); LOADH(hB, jc + 4);
            COMPUTE(wvA, hA);
            COMPUTE(wvB, hB);

            // relu + project onto W3 cols (i, D+i); masked W3 zeroes out
            // cols with deg > i (their garbage h2 is harmless & finite).
            const float* w3 = g_W3pp + (((i << 9) + mycol) << 1);
            float4 wA = __ldg((const float4*)w3);        // (m0,p0,m1,p1)
            float4 wB = __ldg((const float4*)(w3 + 4));  // (m2,p2,m3,p3)
#pragma unroll
            for (int rr = 0; rr < 4; ++rr) {
                float a0, a1, a2, a3;
                unpack2(a0, a1, acc[rr][0]);
                unpack2(a2, a3, acc[rr][1]);
                float h2v;
                h2v = fmaxf(a0, 0.f); mm[rr] += h2v * wA.x; pp[rr] += h2v * wA.y;
                h2v = fmaxf(a1, 0.f); mm[rr] += h2v * wA.z; pp[rr] += h2v * wA.w;
                h2v = fmaxf(a2, 0.f); mm[rr] += h2v * wB.x; pp[rr] += h2v * wB.y;
                h2v = fmaxf(a3, 0.f); mm[rr] += h2v * wB.z; pp[rr] += h2v * wB.w;
            }
        }

        if (any) {
            // reduce over 8 col-groups within the warp (lane bits 2,3,4)
#pragma unroll
            for (int rr = 0; rr < 4; ++rr) {
                mm[rr] += __shfl_xor_sync(0xffffffffu, mm[rr], 4);
                mm[rr] += __shfl_xor_sync(0xffffffffu, mm[rr], 8);
                mm[rr] += __shfl_xor_sync(0xffffffffu, mm[rr], 16);
                pp[rr] += __shfl_xor_sync(0xffffffffu, pp[rr], 4);
                pp[rr] += __shfl_xor_sync(0xffffffffu, pp[rr], 8);
                pp[rr] += __shfl_xor_sync(0xffffffffu, pp[rr], 16);
            }
            if (lane < 4) {
#pragma unroll
                for (int rr = 0; rr < 4; ++rr) {
                    atomicAdd(&red[rbase + rr], mm[rr]);
                    atomicAdd(&red[TM + rbase + rr], pp[rr]);
                }
            }
        }
        __syncthreads();

        if (tid < TM) {
            float mean = red[tid] + b3[i];
            float pres = red[TM + tid] + b3[D + i];
            // stable softplus = max(x,0) + log1p(exp(-|x|))
            float sp = fmaxf(pres, 0.f) + log1pf(expf(-fabsf(pres)));
            float z = mean + sp * eps[(r0 + tid) * D + i];
            out[(r0 + tid) * D + i] = z;
            zsh[tid] = z;
            red[tid] = 0.f;                 // reset for next step
            red[TM + tid] = 0.f;
        }
        __syncthreads();

        // rank-1 h1 update: hidden units with deg >= i+1 (sorted suffix).
        // Rows with deg == i+1 are now finalized -> apply relu in place.
        const int s0  = n2;
        const int fin = cntd(i + 1);
        const int nupd = (H - s0) * TM;
        for (int u = tid; u < nupd; u += NTHREADS) {
            int p = s0 + (u >> 4), r = u & 15;
            float v = h1s[p * TM + r] + zsh[r] * __ldg(&g_W1p[i * H + p]);
            if (p < fin) v = fmaxf(v, 0.f);
            h1s[p * TM + r] = v;
        }
        // top-of-loop __syncthreads orders update before next step's reads
    }
}

extern "C" void kernel_launch(void* const* d_in, const int* in_sizes, int n_in,
                              void* d_out, int out_size) {
    const float* q   = (const float*)d_in[0];  // (4096, 128)
    const float* eps = (const float*)d_in[1];  // (4096, 64)
    const float* W1  = (const float*)d_in[2];  // (192, 512)
    const float* b1  = (const float*)d_in[3];  // (512,)
    const float* W2  = (const float*)d_in[4];  // (512, 512)
    const float* b2  = (const float*)d_in[5];  // (512,)
    const float* W3  = (const float*)d_in[6];  // (512, 128)
    const float* b3  = (const float*)d_in[7];  // (128,)
    float* out = (float*)d_out;                // (4096, 64)

    cudaFuncSetAttribute(made_main, cudaFuncAttributeMaxDynamicSharedMemorySize,
                         SMEM_BYTES);

    prep_kernel<<<408, 256>>>(W1, b1, W2, b2, W3);
    made_main<<<BATCH / TM, NTHREADS, SMEM_BYTES>>>(q, eps, b3, out);
}

// round 7
// speedup vs baseline: 1.1886x; 1.1116x over previous
#include <cuda_runtime.h>
#include <math.h>

#define D 64
#define C 128
#define H 512
#define BATCH 4096
#define TM 16
#define NTHREADS 256

typedef unsigned long long u64;

__device__ __forceinline__ u64 pack2(float lo, float hi) {
    u64 r; asm("mov.b64 %0, {%1, %2};" : "=l"(r) : "f"(lo), "f"(hi)); return r;
}
__device__ __forceinline__ u64 dup2(float x) {
    u64 r; asm("mov.b64 %0, {%1, %1};" : "=l"(r) : "f"(x)); return r;
}
__device__ __forceinline__ void fma2(u64& acc, u64 a, u64 b) {
    asm("fma.rn.f32x2 %0, %1, %2, %0;" : "+l"(acc) : "l"(a), "l"(b));
}
__device__ __forceinline__ void unpack2(float& lo, float& hi, u64 v) {
    asm("mov.b64 {%0, %1}, %2;" : "=f"(lo), "=f"(hi) : "l"(v));
}
__device__ __forceinline__ void cp16(unsigned sa, const void* ga) {
    asm volatile("cp.async.cg.shared.global [%0], [%1], 16;" :: "r"(sa), "l"(ga));
}

// Permuted + masked weights (built by prep kernel each launch; idempotent).
__device__ float g_W1p[(D + C) * H];   // [in][p]  in-major, masked, hidden perm
__device__ float g_W2p[H * H];         // [j][p]   j = reduction dim (sorted), p sorted
__device__ float g_W3pp[D * H * 2];    // [i][p][2] (mean col i, prescale col D+i), masked
__device__ float g_b1p[H];
__device__ float g_b2p[H];

// Hidden degrees: m_h[k] = (k % 63) + 1. Sorted by degree ascending (ties by k).
__device__ __forceinline__ int permk(int p) {
    if (p < 72) { int d = p / 9; int t = p - 9 * d; return d + 63 * t; }
    int q = p - 72; int d8 = q >> 3; int t = q & 7; return 8 + d8 + 63 * t;
}
__device__ __forceinline__ int degp(int p) {
    return (p < 72) ? (p / 9 + 1) : ((p - 72) / 8 + 9);
}
__device__ __forceinline__ int cntd(int d) {
    return (d <= 0) ? 0 : (d <= 8 ? 9 * d : 8 * d + 8);
}

__global__ void prep_kernel(const float* __restrict__ W1, const float* __restrict__ b1,
                            const float* __restrict__ W2, const float* __restrict__ b2,
                            const float* __restrict__ W3) {
    const int NA = (D + C) * H;
    const int NB = H * H;
    const int NC = D * H;
    const int total = NA + NB + NC + 2 * H;
    for (int idx = blockIdx.x * blockDim.x + threadIdx.x; idx < total;
         idx += gridDim.x * blockDim.x) {
        if (idx < NA) {
            int in = idx >> 9, p = idx & 511;
            float m = (in < D) ? ((degp(p) >= in + 1) ? 1.f : 0.f) : 1.f;
            g_W1p[idx] = W1[in * H + permk(p)] * m;
        } else if (idx < NA + NB) {
            int t = idx - NA;
            int j = t >> 9, p = t & 511;
            g_W2p[t] = (degp(p) >= degp(j)) ? W2[permk(j) * H + permk(p)] : 0.f;
        } else if (idx < NA + NB + NC) {
            int t = idx - NA - NB;
            int i = t >> 9, p = t & 511;
            int k = permk(p);
            bool m = (degp(p) <= i);   // m_out = i+1 > deg  <=>  deg <= i
            g_W3pp[t * 2 + 0] = m ? W3[k * (2 * D) + i] : 0.f;
            g_W3pp[t * 2 + 1] = m ? W3[k * (2 * D) + D + i] : 0.f;
        } else {
            int t = idx - NA - NB - NC;
            if (t < H) g_b1p[t] = b1[permk(t)];
            else       g_b2p[t - H] = b2[permk(t - H)];
        }
    }
}

// Dynamic smem layout (floats):
//   h1s[H*TM]     : h1 (pre-act until finalized, then relu'd in place) [p][r] 32KB
//   stage[16384]  : per-warp W2 double buffers (8 warps x 2 x 32x32)          64KB
//                   (ctx[C*TM] overlays stage during init only)
//   zsh[TM], red[2*TM]
#define SMEM_FLOATS (H * TM + 16384 + TM + 2 * TM)
#define SMEM_BYTES (SMEM_FLOATS * 4)

__global__ __launch_bounds__(NTHREADS, 2)
void made_main(const float* __restrict__ qc, const float* __restrict__ eps,
               const float* __restrict__ b3, float* __restrict__ out) {
    extern __shared__ float sm[];
    float* h1s   = sm;                    // [512][16]
    float* stage = sm + H * TM;           // [8 warps][2][32][32]
    float* ctx   = stage;                 // overlay (init only)
    float* zsh   = stage + 16384;         // [16]
    float* red   = zsh + TM;              // [32]

    const int tid  = threadIdx.x;
    const int r0   = blockIdx.x * TM;
    const int warp = tid >> 5, lane = tid & 31;
    const int rg    = lane & 3;               // row group: rows rg*4..rg*4+3
    const int cg    = lane >> 2;              // 0..7: col sub-offset cg*4
    const int rbase = rg << 2;

    float* wstage = stage + warp * 2048;      // this warp's two 1024-float bufs
    const unsigned sbase = (unsigned)__cvta_generic_to_shared(wstage)
                         + (unsigned)((lane >> 3) * 128 + (lane & 7) * 16);
    const int glane = (lane & 7) * 4;         // float offset within 32-col window
    const int grow  = lane >> 3;              // 0..3

    // ---- stage context transposed into overlay: ctx[c][r] ----
    for (int idx = tid; idx < TM * C; idx += NTHREADS) {
        int r = idx >> 7, c = idx & 127;
        ctx[c * TM + r] = qc[(r0 + r) * C + c];
    }
    if (tid < 2 * TM) red[tid] = 0.f;
    __syncthreads();

    // ---- h1_pre init: each thread owns 2 hidden units p, all 16 rows ----
    for (int p = tid; p < H; p += NTHREADS) {
        float acc[TM];
        float b = __ldg(&g_b1p[p]);
#pragma unroll
        for (int r = 0; r < TM; ++r) acc[r] = b;
        for (int c = 0; c < C; ++c) {
            float w = __ldg(&g_W1p[(D + c) * H + p]);
            float4 x0 = *(const float4*)&ctx[c * TM + 0];
            float4 x1 = *(const float4*)&ctx[c * TM + 4];
            float4 x2 = *(const float4*)&ctx[c * TM + 8];
            float4 x3 = *(const float4*)&ctx[c * TM + 12];
            acc[0]  += x0.x * w; acc[1]  += x0.y * w; acc[2]  += x0.z * w; acc[3]  += x0.w * w;
            acc[4]  += x1.x * w; acc[5]  += x1.y * w; acc[6]  += x1.z * w; acc[7]  += x1.w * w;
            acc[8]  += x2.x * w; acc[9]  += x2.y * w; acc[10] += x2.z * w; acc[11] += x2.w * w;
            acc[12] += x3.x * w; acc[13] += x3.y * w; acc[14] += x3.z * w; acc[15] += x3.w * w;
        }
#pragma unroll
        for (int r = 0; r < TM; ++r) h1s[p * TM + r] = acc[r];
    }
    __syncthreads();   // ctx overlay dead before staging begins

    // ---- 64 autoregressive steps ----
    for (int i = 0; i < D; ++i) {
        __syncthreads();   // prev h1 update + red reset visible
        const int n2   = cntd(i);             // needed h2 cols = sorted prefix
        const int nwin = (n2 + 31) >> 5;      // 32-col windows in use (<=16)
        float mm[4] = {0.f, 0.f, 0.f, 0.f};
        float pp[4] = {0.f, 0.f, 0.f, 0.f};
        bool any = false;

        // Serpentine load-balanced window assignment: warp w handles windows
        // {nwin-1-w, nwin-16+w} (those >= 0).
#pragma unroll
        for (int s = 0; s < 2; ++s) {
            const int w = (s == 0) ? (nwin - 1 - warp) : (nwin - 16 + warp);
            if (w < 0) continue;               // warp-uniform predicate
            any = true;
            const int wb = w << 5;
            const int lastneed = min(wb + 31, n2 - 1);
            // multiple of 32, >= 32; rounded rows are exactly zero in needed
            // cols via the masked W2p.
            const int jlimW = min(H, (cntd(degp(lastneed)) + 31) & ~31);
            const int nch = jlimW >> 5;
            const int mycol = wb + (cg << 2);

            // acc[r][cp]: 4 rows x 2 col-pairs, packed f32x2
            float4 b2v = __ldg((const float4*)&g_b2p[mycol]);
            u64 bp0 = pack2(b2v.x, b2v.y), bp1 = pack2(b2v.z, b2v.w);
            u64 acc[4][2];
#pragma unroll
            for (int rr = 0; rr < 4; ++rr) { acc[rr][0] = bp0; acc[rr][1] = bp1; }

            const float* hbase = h1s + rbase;
            const float* gsrc  = g_W2p + wb + glane + (size_t)grow * H;

            // prefetch chunk 0 into buffer 0 (4KB = 8 x 512B warp passes)
#pragma unroll
            for (int u = 0; u < 8; ++u)
                cp16(sbase + u * 512, gsrc + (size_t)(u * 4) * H);
            asm volatile("cp.async.commit_group;");

            for (int c = 0; c < nch; ++c) {
                const float* cur = wstage + ((c & 1) << 10);
                if (c + 1 < nch) {
                    const unsigned dsts = sbase + (((c + 1) & 1) << 12);
                    const float* gnxt = gsrc + (size_t)((c + 1) << 5) * H;
#pragma unroll
                    for (int u = 0; u < 8; ++u)
                        cp16(dsts + u * 512, gnxt + (size_t)(u * 4) * H);
                    asm volatile("cp.async.commit_group;");
                    asm volatile("cp.async.wait_group 1;");
                } else {
                    asm volatile("cp.async.wait_group 0;");
                }
                __syncwarp();

                const float* hj = hbase + ((c << 5) * TM);
                const float* wj = cur + (cg << 2);
#pragma unroll 8
                for (int jj = 0; jj < 32; ++jj) {
                    float4 wq = *(const float4*)&wj[jj << 5];
                    float4 hq = *(const float4*)&hj[jj * TM];
                    u64 w0 = pack2(wq.x, wq.y), w1 = pack2(wq.z, wq.w);
                    u64 d0 = dup2(hq.x), d1 = dup2(hq.y);
                    u64 d2 = dup2(hq.z), d3 = dup2(hq.w);
                    fma2(acc[0][0], d0, w0); fma2(acc[0][1], d0, w1);
                    fma2(acc[1][0], d1, w0); fma2(acc[1][1], d1, w1);
                    fma2(acc[2][0], d2, w0); fma2(acc[2][1], d2, w1);
                    fma2(acc[3][0], d3, w0); fma2(acc[3][1], d3, w1);
                }
                __syncwarp();   // all lanes done reading cur before its reuse
            }

            // relu + project onto W3 cols (i, D+i); masked W3 zeroes out
            // cols with deg > i (their garbage h2 is harmless & finite).
            const float* w3 = g_W3pp + (((i << 9) + mycol) << 1);
            float4 wA = __ldg((const float4*)w3);        // (m0,p0,m1,p1)
            float4 wB = __ldg((const float4*)(w3 + 4));  // (m2,p2,m3,p3)
#pragma unroll
            for (int rr = 0; rr < 4; ++rr) {
                float a0, a1, a2, a3;
                unpack2(a0, a1, acc[rr][0]);
                unpack2(a2, a3, acc[rr][1]);
                float h2v;
                h2v = fmaxf(a0, 0.f); mm[rr] += h2v * wA.x; pp[rr] += h2v * wA.y;
                h2v = fmaxf(a1, 0.f); mm[rr] += h2v * wA.z; pp[rr] += h2v * wA.w;
                h2v = fmaxf(a2, 0.f); mm[rr] += h2v * wB.x; pp[rr] += h2v * wB.y;
                h2v = fmaxf(a3, 0.f); mm[rr] += h2v * wB.z; pp[rr] += h2v * wB.w;
            }
        }

        if (any) {
            // reduce over 8 col-groups within the warp (lane bits 2,3,4)
#pragma unroll
            for (int rr = 0; rr < 4; ++rr) {
                mm[rr] += __shfl_xor_sync(0xffffffffu, mm[rr], 4);
                mm[rr] += __shfl_xor_sync(0xffffffffu, mm[rr], 8);
                mm[rr] += __shfl_xor_sync(0xffffffffu, mm[rr], 16);
                pp[rr] += __shfl_xor_sync(0xffffffffu, pp[rr], 4);
                pp[rr] += __shfl_xor_sync(0xffffffffu, pp[rr], 8);
                pp[rr] += __shfl_xor_sync(0xffffffffu, pp[rr], 16);
            }
            if (lane < 4) {
#pragma unroll
                for (int rr = 0; rr < 4; ++rr) {
                    atomicAdd(&red[rbase + rr], mm[rr]);
                    atomicAdd(&red[TM + rbase + rr], pp[rr]);
                }
            }
        }
        __syncthreads();

        if (tid < TM) {
            float mean = red[tid] + b3[i];
            float pres = red[TM + tid] + b3[D + i];
            // stable softplus = max(x,0) + log1p(exp(-|x|))
            float sp = fmaxf(pres, 0.f) + log1pf(expf(-fabsf(pres)));
            float z = mean + sp * eps[(r0 + tid) * D + i];
            out[(r0 + tid) * D + i] = z;
            zsh[tid] = z;
            red[tid] = 0.f;                 // reset for next step
            red[TM + tid] = 0.f;
        }
        __syncthreads();

        // rank-1 h1 update: hidden units with deg >= i+1 (sorted suffix).
        // Rows with deg == i+1 are now finalized -> apply relu in place.
        const int s0  = n2;
        const int fin = cntd(i + 1);
        const int nupd = (H - s0) * TM;
        for (int u = tid; u < nupd; u += NTHREADS) {
            int p = s0 + (u >> 4), r = u & 15;
            float v = h1s[p * TM + r] + zsh[r] * __ldg(&g_W1p[i * H + p]);
            if (p < fin) v = fmaxf(v, 0.f);
            h1s[p * TM + r] = v;
        }
        // top-of-loop __syncthreads orders update before next step's reads
    }
}

extern "C" void kernel_launch(void* const* d_in, const int* in_sizes, int n_in,
                              void* d_out, int out_size) {
    const float* q   = (const float*)d_in[0];  // (4096, 128)
    const float* eps = (const float*)d_in[1];  // (4096, 64)
    const float* W1  = (const float*)d_in[2];  // (192, 512)
    const float* b1  = (const float*)d_in[3];  // (512,)
    const float* W2  = (const float*)d_in[4];  // (512, 512)
    const float* b2  = (const float*)d_in[5];  // (512,)
    const float* W3  = (const float*)d_in[6];  // (512, 128)
    const float* b3  = (const float*)d_in[7];  // (128,)
    float* out = (float*)d_out;                // (4096, 64)

    cudaFuncSetAttribute(made_main, cudaFuncAttributeMaxDynamicSharedMemorySize,
                         SMEM_BYTES);

    prep_kernel<<<408, 256>>>(W1, b1, W2, b2, W3);
    made_main<<<BATCH / TM, NTHREADS, SMEM_BYTES>>>(q, eps, b3, out);
}

// round 8
// speedup vs baseline: 2.4056x; 2.0238x over previous
#include <cuda_runtime.h>
#include <math.h>

#define D 64
#define C 128
#define H 512
#define BATCH 4096
#define TM 16
#define NTHREADS 256
#define HS 520   // padded h1T row stride in floats (kills LDS bank conflicts)

typedef unsigned long long u64;

__device__ __forceinline__ u64 pack2(float lo, float hi) {
    u64 r; asm("mov.b64 %0, {%1, %2};" : "=l"(r) : "f"(lo), "f"(hi)); return r;
}
__device__ __forceinline__ void fma2(u64& acc, u64 a, u64 b) {
    asm("fma.rn.f32x2 %0, %1, %2, %0;" : "+l"(acc) : "l"(a), "l"(b));
}
__device__ __forceinline__ void unpack2(float& lo, float& hi, u64 v) {
    asm("mov.b64 {%0, %1}, %2;" : "=f"(lo), "=f"(hi) : "l"(v));
}

// Permuted + masked weights (built by prep kernel each launch; idempotent).
__device__ float g_W1p[(D + C) * H];   // [in][p]  in-major, masked, hidden perm
__device__ float g_W2pT[H * H];        // [p][j]   TRANSPOSED masked W2 (j = reduction)
__device__ float g_W3pp[D * H * 2];    // [i][p][2] (mean col i, prescale col D+i), masked
__device__ float g_b1p[H];
__device__ float g_b2p[H];

// Hidden degrees: m_h[k] = (k % 63) + 1. Sorted by degree ascending (ties by k).
__device__ __forceinline__ int permk(int p) {
    if (p < 72) { int d = p / 9; int t = p - 9 * d; return d + 63 * t; }
    int q = p - 72; int d8 = q >> 3; int t = q & 7; return 8 + d8 + 63 * t;
}
__device__ __forceinline__ int degp(int p) {
    return (p < 72) ? (p / 9 + 1) : ((p - 72) / 8 + 9);
}
__device__ __forceinline__ int cntd(int d) {
    return (d <= 0) ? 0 : (d <= 8 ? 9 * d : 8 * d + 8);
}

__global__ void prep_kernel(const float* __restrict__ W1, const float* __restrict__ b1,
                            const float* __restrict__ W2, const float* __restrict__ b2,
                            const float* __restrict__ W3) {
    const int NA = (D + C) * H;
    const int NB = H * H;
    const int NC = D * H;
    const int total = NA + NB + NC + 2 * H;
    for (int idx = blockIdx.x * blockDim.x + threadIdx.x; idx < total;
         idx += gridDim.x * blockDim.x) {
        if (idx < NA) {
            int in = idx >> 9, p = idx & 511;
            float m = (in < D) ? ((degp(p) >= in + 1) ? 1.f : 0.f) : 1.f;
            g_W1p[idx] = W1[in * H + permk(p)] * m;
        } else if (idx < NA + NB) {
            int t = idx - NA;
            int p = t >> 9, j = t & 511;     // TRANSPOSED: [p][j]
            g_W2pT[t] = (degp(p) >= degp(j)) ? W2[permk(j) * H + permk(p)] : 0.f;
        } else if (idx < NA + NB + NC) {
            int t = idx - NA - NB;
            int i = t >> 9, p = t & 511;
            int k = permk(p);
            bool m = (degp(p) <= i);   // m_out = i+1 > deg  <=>  deg <= i
            g_W3pp[t * 2 + 0] = m ? W3[k * (2 * D) + i] : 0.f;
            g_W3pp[t * 2 + 1] = m ? W3[k * (2 * D) + D + i] : 0.f;
        } else {
            int t = idx - NA - NB - NC;
            if (t < H) g_b1p[t] = b1[permk(t)];
            else       g_b2p[t - H] = b2[permk(t - H)];
        }
    }
}

// Dynamic smem layout (floats):
//   h1T[TM][HS]  : h1, row-contiguous j, padded stride                8320
//   h2s[H][TM]   : cached relu'd h2 columns (ctx overlays during init) 8192
//   epss[TM][D]  : staged eps rows                                     1024
//   b3s[2D]      : staged b3                                            128
//   red[32]      : per-row mean/prescale partials
#define SMEM_FLOATS (TM * HS + H * TM + TM * D + 2 * D + 32)
#define SMEM_BYTES (SMEM_FLOATS * 4)

__global__ __launch_bounds__(NTHREADS, 2)
void made_main(const float* __restrict__ qc, const float* __restrict__ eps,
               const float* __restrict__ b3g, float* __restrict__ out) {
    extern __shared__ float sm[];
    float* h1T  = sm;                  // [16][520]
    float* h2s  = sm + TM * HS;        // [512][16]
    float* ctx  = h2s;                 // overlay, init only: [128][16]
    float* epss = h2s + H * TM;        // [16][64]
    float* b3s  = epss + TM * D;       // [128]
    float* red  = b3s + 2 * D;         // [32]

    const int tid  = threadIdx.x;
    const int r0   = blockIdx.x * TM;
    const int warp = tid >> 5, lane = tid & 31;

    // ---- stage ctx (transposed [c][r]), eps rows, b3; zero red ----
    for (int idx = tid; idx < TM * C; idx += NTHREADS) {
        int r = idx >> 7, c = idx & 127;
        ctx[c * TM + r] = qc[(r0 + r) * C + c];
    }
    for (int idx = tid; idx < TM * D; idx += NTHREADS)
        epss[idx] = eps[r0 * D + idx];           // contiguous rows
    for (int idx = tid; idx < 2 * D; idx += NTHREADS)
        b3s[idx] = b3g[idx];
    if (tid < 32) red[tid] = 0.f;
    __syncthreads();

    // ---- h1_pre init: thread owns hidden unit p, all 16 rows in regs ----
    for (int p = tid; p < H; p += NTHREADS) {
        float acc[TM];
        float b = __ldg(&g_b1p[p]);
#pragma unroll
        for (int r = 0; r < TM; ++r) acc[r] = b;
        for (int c = 0; c < C; ++c) {
            float w = __ldg(&g_W1p[(D + c) * H + p]);
            float4 x0 = *(const float4*)&ctx[c * TM + 0];
            float4 x1 = *(const float4*)&ctx[c * TM + 4];
            float4 x2 = *(const float4*)&ctx[c * TM + 8];
            float4 x3 = *(const float4*)&ctx[c * TM + 12];
            acc[0]  += x0.x * w; acc[1]  += x0.y * w; acc[2]  += x0.z * w; acc[3]  += x0.w * w;
            acc[4]  += x1.x * w; acc[5]  += x1.y * w; acc[6]  += x1.z * w; acc[7]  += x1.w * w;
            acc[8]  += x2.x * w; acc[9]  += x2.y * w; acc[10] += x2.z * w; acc[11] += x2.w * w;
            acc[12] += x3.x * w; acc[13] += x3.y * w; acc[14] += x3.z * w; acc[15] += x3.w * w;
        }
#pragma unroll
        for (int r = 0; r < TM; ++r) h1T[r * HS + p] = acc[r];  // lanes: consec p, conflict-free
    }

    // ---- 64 autoregressive steps ----
    for (int i = 0; i < D; ++i) {
        __syncthreads();   // h2s from prev Phase C (or ctx dead), red reset visible
        const int n2  = cntd(i);
        const int fin = cntd(i + 1);

        // ---- Phase A: projection over cached h2 prefix [0, n2) ----
        {
            const int pl = tid >> 4, r = tid & 15;
            float mmv = 0.f, ppv = 0.f;
            for (int p = pl; p < n2; p += 16) {
                float hv = h2s[p * TM + r];
                float2 w3 = *(const float2*)&g_W3pp[(((i << 9) + p)) << 1];
                mmv += hv * w3.x; ppv += hv * w3.y;
            }
            mmv += __shfl_xor_sync(0xffffffffu, mmv, 16);
            ppv += __shfl_xor_sync(0xffffffffu, ppv, 16);
            if (lane < 16) {
                atomicAdd(&red[lane], mmv);
                atomicAdd(&red[16 + lane], ppv);
            }
        }
        __syncthreads();   // red complete

        // ---- z for this warp's two rows (computed redundantly per warp) ----
        const int ra = warp * 2, rb = ra + 1;
        float za, zb;
        {
            float mean = red[ra] + b3s[i];
            float pres = red[16 + ra] + b3s[D + i];
            float sp = fmaxf(pres, 0.f) + log1pf(expf(-fabsf(pres)));
            za = mean + sp * epss[ra * D + i];
            mean = red[rb] + b3s[i];
            pres = red[16 + rb] + b3s[D + i];
            sp = fmaxf(pres, 0.f) + log1pf(expf(-fabsf(pres)));
            zb = mean + sp * epss[rb * D + i];
        }
        if (tid < TM) {    // one thread per row writes the output sample
            float mean = red[tid] + b3s[i];
            float pres = red[16 + tid] + b3s[D + i];
            float sp = fmaxf(pres, 0.f) + log1pf(expf(-fabsf(pres)));
            out[(r0 + tid) * D + i] = mean + sp * epss[tid * D + i];
        }

        // ---- Phase B: rank-1 h1 update, suffix rows deg >= i+1; relu deg==i+1 ----
        for (int p = n2 + lane; p < H; p += 32) {
            float wv = __ldg(&g_W1p[i * H + p]);
            float va = h1T[ra * HS + p] + za * wv;
            float vb = h1T[rb * HS + p] + zb * wv;
            if (p < fin) { va = fmaxf(va, 0.f); vb = fmaxf(vb, 0.f); }
            h1T[ra * HS + p] = va;
            h1T[rb * HS + p] = vb;
        }
        __syncthreads();   // h1 final through deg i+1

        // ---- Phase C: compute NEW h2 columns (deg == i+1) once, cache in h2s ----
        if (tid < 32) red[tid] = 0.f;   // all red readers passed the barrier above
        if (i < D - 1) {
            const int ncol = fin - n2;            // 8 or 9
            if (tid < ncol * TM) {
                const int c = tid >> 4, rr = tid & 15;
                const int p = n2 + c;
                const float* hrow = h1T + rr * HS;
                const float* wc   = g_W2pT + (size_t)p * H;
                const int jlim = (fin + 7) & ~7;  // pad rows are masked-zero in W2pT
                u64 a0 = 0, a1 = 0, a2 = 0, a3 = 0;
#pragma unroll 2
                for (int j = 0; j < jlim; j += 8) {
                    float4 ha = *(const float4*)&hrow[j];
                    float4 hb = *(const float4*)&hrow[j + 4];
                    float4 wa = __ldg((const float4*)&wc[j]);
                    float4 wb = __ldg((const float4*)&wc[j + 4]);
                    fma2(a0, pack2(ha.x, ha.y), pack2(wa.x, wa.y));
                    fma2(a1, pack2(ha.z, ha.w), pack2(wa.z, wa.w));
                    fma2(a2, pack2(hb.x, hb.y), pack2(wb.x, wb.y));
                    fma2(a3, pack2(hb.z, hb.w), pack2(wb.z, wb.w));
                }
                float l0, h0, l1, h1v, l2, h2v, l3, h3;
                unpack2(l0, h0, a0); unpack2(l1, h1v, a1);
                unpack2(l2, h2v, a2); unpack2(l3, h3, a3);
                float s = __ldg(&g_b2p[p]) + ((l0 + h0) + (l1 + h1v))
                                           + ((l2 + h2v) + (l3 + h3));
                h2s[p * TM + rr] = fmaxf(s, 0.f);   // store relu'd
            }
        }
        // top-of-loop barrier orders h2s writes before next step's Phase A
    }
}

extern "C" void kernel_launch(void* const* d_in, const int* in_sizes, int n_in,
                              void* d_out, int out_size) {
    const float* q   = (const float*)d_in[0];  // (4096, 128)
    const float* eps = (const float*)d_in[1];  // (4096, 64)
    const float* W1  = (const float*)d_in[2];  // (192, 512)
    const float* b1  = (const float*)d_in[3];  // (512,)
    const float* W2  = (const float*)d_in[4];  // (512, 512)
    const float* b2  = (const float*)d_in[5];  // (512,)
    const float* W3  = (const float*)d_in[6];  // (512, 128)
    const float* b3  = (const float*)d_in[7];  // (128,)
    float* out = (float*)d_out;                // (4096, 64)

    cudaFuncSetAttribute(made_main, cudaFuncAttributeMaxDynamicSharedMemorySize,
                         SMEM_BYTES);

    prep_kernel<<<408, 256>>>(W1, b1, W2, b2, W3);
    made_main<<<BATCH / TM, NTHREADS, SMEM_BYTES>>>(q, eps, b3, out);
}

// round 10
// speedup vs baseline: 4.3428x; 1.8053x over previous
#include <cuda_runtime.h>
#include <math.h>

#define D 64
#define C 128
#define H 512
#define BATCH 4096
#define TM 16
#define NTHREADS 256
#define HS 518          // h1T row stride: 518 mod 32 = 6 -> conflict-free f32x2 reads
#define STAGE_FLOATS 4096

typedef unsigned long long u64;

__device__ __forceinline__ u64 pack2(float lo, float hi) {
    u64 r; asm("mov.b64 %0, {%1, %2};" : "=l"(r) : "f"(lo), "f"(hi)); return r;
}
__device__ __forceinline__ void fma2(u64& acc, u64 a, u64 b) {
    asm("fma.rn.f32x2 %0, %1, %2, %0;" : "+l"(acc) : "l"(a), "l"(b));
}
__device__ __forceinline__ void unpack2(float& lo, float& hi, u64 v) {
    asm("mov.b64 {%0, %1}, %2;" : "=f"(lo), "=f"(hi) : "l"(v));
}
__device__ __forceinline__ void cp16(unsigned sa, const void* ga) {
    asm volatile("cp.async.cg.shared.global [%0], [%1], 16;" :: "r"(sa), "l"(ga));
}

// Permuted + masked weights (built by prep kernel each launch; idempotent).
__device__ float g_W1p[(D + C) * H];   // [in][p]  in-major, masked, hidden perm
__device__ float g_W2pT[H * H];        // [p][j]   TRANSPOSED masked W2 (j = reduction)
__device__ float g_W3pp[D * H * 2];    // [i][p][2] (mean col i, prescale col D+i), masked
__device__ float g_b1p[H];
__device__ float g_b2p[H];

// Hidden degrees: m_h[k] = (k % 63) + 1. Sorted by degree ascending (ties by k).
__device__ __forceinline__ int permk(int p) {
    if (p < 72) { int d = p / 9; int t = p - 9 * d; return d + 63 * t; }
    int q = p - 72; int d8 = q >> 3; int t = q & 7; return 8 + d8 + 63 * t;
}
__device__ __forceinline__ int degp(int p) {
    return (p < 72) ? (p / 9 + 1) : ((p - 72) / 8 + 9);
}
__device__ __forceinline__ int cntd(int d) {
    return (d <= 0) ? 0 : (d <= 8 ? 9 * d : 8 * d + 8);
}

__global__ void prep_kernel(const float* __restrict__ W1, const float* __restrict__ b1,
                            const float* __restrict__ W2, const float* __restrict__ b2,
                            const float* __restrict__ W3) {
    const int NA = (D + C) * H;
    const int NB = H * H;
    const int NC = D * H;
    const int total = NA + NB + NC + 2 * H;
    for (int idx = blockIdx.x * blockDim.x + threadIdx.x; idx < total;
         idx += gridDim.x * blockDim.x) {
        if (idx < NA) {
            int in = idx >> 9, p = idx & 511;
            float m = (in < D) ? ((degp(p) >= in + 1) ? 1.f : 0.f) : 1.f;
            g_W1p[idx] = W1[in * H + permk(p)] * m;
        } else if (idx < NA + NB) {
            int t = idx - NA;
            int p = t >> 9, j = t & 511;     // TRANSPOSED: [p][j]
            g_W2pT[t] = (degp(p) >= degp(j)) ? W2[permk(j) * H + permk(p)] : 0.f;
        } else if (idx < NA + NB + NC) {
            int t = idx - NA - NB;
            int i = t >> 9, p = t & 511;
            int k = permk(p);
            bool m = (degp(p) <= i);   // m_out = i+1 > deg  <=>  deg <= i
            g_W3pp[t * 2 + 0] = m ? W3[k * (2 * D) + i] : 0.f;
            g_W3pp[t * 2 + 1] = m ? W3[k * (2 * D) + D + i] : 0.f;
        } else {
            int t = idx - NA - NB - NC;
            if (t < H) g_b1p[t] = b1[permk(t)];
            else       g_b2p[t - H] = b2[permk(t - H)];
        }
    }
}

// Dynamic smem layout (floats):
//   h1T[TM][HS]       8288   h1, row-contiguous j
//   h2s[H][TM]        8192   cached relu'd h2 cols (ctx overlay during init)
//   stage[4096]              cp.async W2pT tile for this step
//   w1s[H]             512   cp.async W1p row i
//   epss[TM][D]       1024
//   b3s[2D]            128
//   red[32]             32
#define SMEM_FLOATS (TM * HS + H * TM + STAGE_FLOATS + H + TM * D + 2 * D + 32)
#define SMEM_BYTES (SMEM_FLOATS * 4)

__global__ __launch_bounds__(NTHREADS, 2)
void made_main(const float* __restrict__ qc, const float* __restrict__ eps,
               const float* __restrict__ b3g, float* __restrict__ out) {
    extern __shared__ float sm[];
    float* h1T   = sm;                     // [16][518]
    float* h2s   = sm + TM * HS;           // [512][16]
    float* ctx   = h2s;                    // overlay, init only: [128][16]
    float* stage = h2s + H * TM;           // [4096]
    float* w1s   = stage + STAGE_FLOATS;   // [512]
    float* epss  = w1s + H;                // [16][64]
    float* b3s   = epss + TM * D;          // [128]
    float* red   = b3s + 2 * D;            // [32]

    const int tid  = threadIdx.x;
    const int r0   = blockIdx.x * TM;
    const int warp = tid >> 5, lane = tid & 31;

    const unsigned stage_sa = (unsigned)__cvta_generic_to_shared(stage);
    const unsigned w1_sa    = (unsigned)__cvta_generic_to_shared(w1s);

    // ---- stage ctx (transposed [c][r]), eps rows, b3; zero red ----
    for (int idx = tid; idx < TM * C; idx += NTHREADS) {
        int r = idx >> 7, c = idx & 127;
        ctx[c * TM + r] = qc[(r0 + r) * C + c];
    }
    for (int idx = tid; idx < TM * D; idx += NTHREADS)
        epss[idx] = eps[r0 * D + idx];           // contiguous rows
    for (int idx = tid; idx < 2 * D; idx += NTHREADS)
        b3s[idx] = b3g[idx];
    if (tid < 32) red[tid] = 0.f;
    __syncthreads();

    // ---- h1_pre init: thread owns hidden unit p, all 16 rows in regs ----
    for (int p = tid; p < H; p += NTHREADS) {
        float acc[TM];
        float b = __ldg(&g_b1p[p]);
#pragma unroll
        for (int r = 0; r < TM; ++r) acc[r] = b;
        for (int c = 0; c < C; ++c) {
            float w = __ldg(&g_W1p[(D + c) * H + p]);
            float4 x0 = *(const float4*)&ctx[c * TM + 0];
            float4 x1 = *(const float4*)&ctx[c * TM + 4];
            float4 x2 = *(const float4*)&ctx[c * TM + 8];
            float4 x3 = *(const float4*)&ctx[c * TM + 12];
            acc[0]  += x0.x * w; acc[1]  += x0.y * w; acc[2]  += x0.z * w; acc[3]  += x0.w * w;
            acc[4]  += x1.x * w; acc[5]  += x1.y * w; acc[6]  += x1.z * w; acc[7]  += x1.w * w;
            acc[8]  += x2.x * w; acc[9]  += x2.y * w; acc[10] += x2.z * w; acc[11] += x2.w * w;
            acc[12] += x3.x * w; acc[13] += x3.y * w; acc[14] += x3.z * w; acc[15] += x3.w * w;
        }
#pragma unroll
        for (int r = 0; r < TM; ++r) h1T[r * HS + p] = acc[r];
    }

    // ---- 64 autoregressive steps ----
    for (int i = 0; i < D; ++i) {
        __syncthreads();   // h2s/stage from prev step consumed; red reset visible
        const int n2   = cntd(i);
        const int fin  = cntd(i + 1);
        const int ncol = fin - n2;                 // 8 or 9
        const int jlim = (fin + 7) & ~7;           // pad rows masked-zero in W2pT

        // ---- prefetch W1p row i (group 0), then W2pT tile (group 1) ----
        if (tid < 128)
            cp16(w1_sa + tid * 16, g_W1p + i * H + tid * 4);
        asm volatile("cp.async.commit_group;");
        if (i < D - 1) {
            const int nunit = (ncol * jlim) >> 2;  // 16B units
            const int upr = jlim >> 2;             // units per row
            for (int u = tid; u < nunit; u += NTHREADS) {
                int c = u / upr, jo = (u - c * upr) << 2;
                cp16(stage_sa + ((c * jlim + jo) << 2),
                     g_W2pT + (size_t)(n2 + c) * H + jo);
            }
        }
        asm volatile("cp.async.commit_group;");

        // ---- Phase A: projection over cached h2 prefix [0, n2) ----
        {
            const int pl = tid >> 4, r = tid & 15;
            float mmv = 0.f, ppv = 0.f;
            for (int p = pl; p < n2; p += 16) {
                float hv = h2s[p * TM + r];
                float2 w3 = *(const float2*)&g_W3pp[(((i << 9) + p)) << 1];
                mmv += hv * w3.x; ppv += hv * w3.y;
            }
            mmv += __shfl_xor_sync(0xffffffffu, mmv, 16);
            ppv += __shfl_xor_sync(0xffffffffu, ppv, 16);
            if (lane < 16) {
                atomicAdd(&red[lane], mmv);
                atomicAdd(&red[16 + lane], ppv);
            }
        }
        asm volatile("cp.async.wait_group 1;");   // W1 row landed (own copies)
        __syncthreads();   // red complete + w1s visible to all

        // ---- z for this warp's two rows (computed redundantly per warp) ----
        const int ra = warp * 2, rb = ra + 1;
        float za, zb;
        {
            float mean = red[ra] + b3s[i];
            float pres = red[16 + ra] + b3s[D + i];
            float sp = fmaxf(pres, 0.f) + log1pf(expf(-fabsf(pres)));
            za = mean + sp * epss[ra * D + i];
            mean = red[rb] + b3s[i];
            pres = red[16 + rb] + b3s[D + i];
            sp = fmaxf(pres, 0.f) + log1pf(expf(-fabsf(pres)));
            zb = mean + sp * epss[rb * D + i];
        }
        if (tid < TM) {    // one thread per row writes the output sample
            float mean = red[tid] + b3s[i];
            float pres = red[16 + tid] + b3s[D + i];
            float sp = fmaxf(pres, 0.f) + log1pf(expf(-fabsf(pres)));
            out[(r0 + tid) * D + i] = mean + sp * epss[tid * D + i];
        }

        // ---- Phase B: rank-1 h1 update, suffix rows deg >= i+1 (from w1s) ----
        for (int p = n2 + lane; p < H; p += 32) {
            float wv = w1s[p];
            float va = h1T[ra * HS + p] + za * wv;
            float vb = h1T[rb * HS + p] + zb * wv;
            if (p < fin) { va = fmaxf(va, 0.f); vb = fmaxf(vb, 0.f); }
            h1T[ra * HS + p] = va;
            h1T[rb * HS + p] = vb;
        }
        asm volatile("cp.async.wait_group 0;");   // W2 tile landed (own copies)
        __syncthreads();   // h1 final thru deg i+1 + stage visible to all

        // ---- Phase C: compute NEW h2 columns (deg == i+1) from staged W2 ----
        if (tid < 32) red[tid] = 0.f;   // all red readers passed the barrier
        if (i < D - 1 && tid < ncol * TM) {
            const int c = tid >> 4, rr = tid & 15;
            const int p = n2 + c;
            const float* hrow = h1T + rr * HS;
            const float* wc   = stage + c * jlim;
            u64 a0 = 0, a1 = 0, a2 = 0, a3 = 0;
#pragma unroll 2
            for (int j = 0; j < jlim; j += 8) {
                float2 h0 = *(const float2*)&hrow[j];
                float2 h1v = *(const float2*)&hrow[j + 2];
                float2 h2v = *(const float2*)&hrow[j + 4];
                float2 h3 = *(const float2*)&hrow[j + 6];
                float4 wa = *(const float4*)&wc[j];        // broadcast
                float4 wb = *(const float4*)&wc[j + 4];    // broadcast
                fma2(a0, pack2(h0.x, h0.y), pack2(wa.x, wa.y));
                fma2(a1, pack2(h1v.x, h1v.y), pack2(wa.z, wa.w));
                fma2(a2, pack2(h2v.x, h2v.y), pack2(wb.x, wb.y));
                fma2(a3, pack2(h3.x, h3.y), pack2(wb.z, wb.w));
            }
            float l0, u0, l1, u1, l2, u2, l3, u3;
            unpack2(l0, u0, a0); unpack2(l1, u1, a1);
            unpack2(l2, u2, a2); unpack2(l3, u3, a3);
            float s = __ldg(&g_b2p[p]) + ((l0 + u0) + (l1 + u1))
                                       + ((l2 + u2) + (l3 + u3));
            h2s[p * TM + rr] = fmaxf(s, 0.f);   // store relu'd
        }
        // top-of-loop barrier orders h2s/stage before next step
    }
}

extern "C" void kernel_launch(void* const* d_in, const int* in_sizes, int n_in,
                              void* d_out, int out_size) {
    const float* q   = (const float*)d_in[0];  // (4096, 128)
    const float* eps = (const float*)d_in[1];  // (4096, 64)
    const float* W1  = (const float*)d_in[2];  // (192, 512)
    const float* b1  = (const float*)d_in[3];  // (512,)
    const float* W2  = (const float*)d_in[4];  // (512, 512)
    const float* b2  = (const float*)d_in[5];  // (512,)
    const float* W3  = (const float*)d_in[6];  // (512, 128)
    const float* b3  = (const float*)d_in[7];  // (128,)
    float* out = (float*)d_out;                // (4096, 64)

    cudaFuncSetAttribute(made_main, cudaFuncAttributeMaxDynamicSharedMemorySize,
                         SMEM_BYTES);

    prep_kernel<<<408, 256>>>(W1, b1, W2, b2, W3);
    made_main<<<BATCH / TM, NTHREADS, SMEM_BYTES>>>(q, eps, b3, out);
}